// round 14
// baseline (speedup 1.0000x reference)
#include <cuda_runtime.h>
#include <math.h>
#include <stdint.h>

#define Bb 8
#define Nn 4096
#define DIM 768
#define HEADS 6
#define HD 128
#define QKVC 1536
#define NCHUNK 8
#define CHUNK (Nn/NCHUNK)   // 512
#define EPS 1e-12f

// ------------------ scratch (device globals: no allocs allowed) ------------------
__device__ float g_qkv[(size_t)Bb*Nn*QKVC];          // 201 MB (normal row-major)
__device__ float g_xr[(size_t)Bb*Nn*DIM];            // packed-A x (tf32), 100 MB
__device__ float g_wqkv[DIM*QKVC];                   // packed-B W_qkv (tf32)
__device__ float g_wproj[DIM*DIM];                   // packed-B W_proj (tf32)
__device__ float g_nsum[Bb*QKVC];
__device__ float g_inv[Bb*QKVC];
__device__ float g_P[NCHUNK][Bb*HEADS*HD*HD];        // attn partials, 25 MB
__device__ float g_attn[(size_t)Bb*HEADS*HD*HD];     // softmaxed attn (tf32-rounded)
__device__ float g_tmp[(size_t)Bb*Nn*DIM];           // packed-A pre-projection output

// ------------------ helpers ------------------
__device__ __forceinline__ uint32_t f2tf32(float x) {
    uint32_t r;
    asm("cvt.rna.tf32.f32 %0, %1;" : "=r"(r) : "f"(x));
    return r;
}
__device__ __forceinline__ float roundtf(float x) {
    return __uint_as_float(f2tf32(x));
}
__device__ __forceinline__ void cp16(void* dst, const void* src) {
    uint32_t d = (uint32_t)__cvta_generic_to_shared(dst);
    asm volatile("cp.async.cg.shared.global [%0], [%1], 16;" :: "r"(d), "l"(src));
}
__device__ __forceinline__ void mma4(float* c, const uint4& a, uint32_t b0, uint32_t b1) {
    asm volatile(
        "mma.sync.aligned.m16n8k8.row.col.f32.tf32.tf32.f32 "
        "{%0,%1,%2,%3},{%4,%5,%6,%7},{%8,%9},{%0,%1,%2,%3};"
        : "+f"(c[0]), "+f"(c[1]), "+f"(c[2]), "+f"(c[3])
        : "r"(a.x), "r"(a.y), "r"(a.z), "r"(a.w), "r"(b0), "r"(b1));
}

// packed-A element index: A[M][K] -> tiles [M/128][K/32][4096 floats]
// within tile: idx = (((ks*8+mg)*8+g)*4+tg)*4 + j,  j = khalf*2 + rowhalf
__device__ __forceinline__ size_t aidx(size_t m, int k, int KT) {
    size_t mt = m >> 7; int ml = (int)(m & 127);
    int kt = k >> 5, kl = k & 31;
    int ks = kl >> 3, kk = kl & 7, tg = kk & 3, kh = kk >> 2;
    int mg = ml >> 4, rh = (ml >> 3) & 1, gg = ml & 7;
    return ((mt * KT + kt) << 12) + (((((ks << 3) + mg) << 3) + gg) << 4) + (tg << 2) + (kh * 2 + rh);
}

// ------------------ pack kernels (round to tf32 + fragment order) ------------------
__global__ void pack_a(const float* __restrict__ src, float* __restrict__ dst,
                       int M, int K)
{
    int KT = K >> 5;
    size_t q = (size_t)blockIdx.x * 256 + threadIdx.x;
    size_t total = ((size_t)M * K) >> 2;
    if (q >= total) return;
    size_t tile = q >> 10;
    int qi = (int)(q & 1023);
    size_t mt = tile / KT; int kt = (int)(tile % KT);
    int tg = qi & 3, gg = (qi >> 2) & 7, mg = (qi >> 5) & 7, ks = qi >> 8;
    float4 o; float* po = (float*)&o;
#pragma unroll
    for (int j = 0; j < 4; j++) {
        int kh = j >> 1, rh = j & 1;
        size_t m = mt * 128 + mg * 16 + rh * 8 + gg;
        int k = kt * 32 + ks * 8 + kh * 4 + tg;
        po[j] = roundtf(src[m * K + k]);
    }
    ((float4*)dst)[q] = o;
}

// B pack: src [K,N] row-major -> packed tiles [N/128][K/32][4096]
// within tile: idx = (((kp*16+ng)*8+g)*4+tg)*4 + j,  j = (ks%2)*2 + khalf
__global__ void pack_b(const float* __restrict__ src, float* __restrict__ dst,
                       int K, int N)
{
    int KT = K >> 5;
    size_t q = (size_t)blockIdx.x * 256 + threadIdx.x;
    size_t total = ((size_t)K * N) >> 2;
    if (q >= total) return;
    size_t tile = q >> 10;
    int qi = (int)(q & 1023);
    size_t nt0 = tile / KT; int kt = (int)(tile % KT);
    int tg = qi & 3, gg = (qi >> 2) & 7, ng = (qi >> 5) & 15, kp = qi >> 9;
    float4 o; float* po = (float*)&o;
#pragma unroll
    for (int j = 0; j < 4; j++) {
        int s = j >> 1, kh = j & 1;
        int k = kt * 32 + (kp * 2 + s) * 8 + kh * 4 + tg;
        size_t n = nt0 * 128 + ng * 8 + gg;
        po[j] = roundtf(src[(size_t)k * N + n]);
    }
    ((float4*)dst)[q] = o;
}

// ------------------ packed tf32 GEMM: 128x256 block tile, 8 warps of 64x64 ------------------
#define STAGES 3
#define TILE_F 12288   // floats per stage: A 4096 + B0 4096 + B1 4096
#define GEMM_SMEM (STAGES * TILE_F * 4)

template<int BIAS>
__global__ __launch_bounds__(256, 1)
void tf32gemm_pk(const float* __restrict__ A, const float* __restrict__ B,
                 const float* __restrict__ bias, float* __restrict__ C,
                 int M, int N, int K)
{
    extern __shared__ float sm[];
    const int KT = K >> 5;
    const int tid  = threadIdx.x;
    const int warp = tid >> 5, lane = tid & 31;
    const int wm   = warp >> 2, wn = warp & 3;      // warp grid 2(m) x 4(n), tile 64x64
    const int g    = lane >> 2, tg = lane & 3;

    const float* Atile  = A + (size_t)blockIdx.y * KT * 4096;
    const float* Btile0 = B + (size_t)(blockIdx.x * 2 + 0) * KT * 4096;
    const float* Btile1 = B + (size_t)(blockIdx.x * 2 + 1) * KT * 4096;

    float acc[4][8][4];
#pragma unroll
    for (int mt = 0; mt < 4; mt++)
#pragma unroll
        for (int nt = 0; nt < 8; nt++)
#pragma unroll
            for (int i = 0; i < 4; i++) acc[mt][nt][i] = 0.f;

    // stage copy: 12288 floats = 3072 float4, 256 threads -> 12 cp16 each
    auto stage_copy = [&](int kt, int buf) {
        float* d = sm + buf * TILE_F;
        const float* sa  = Atile  + (size_t)kt * 4096;
        const float* sb0 = Btile0 + (size_t)kt * 4096;
        const float* sb1 = Btile1 + (size_t)kt * 4096;
#pragma unroll
        for (int i = 0; i < 4; i++)
            cp16(d + (size_t)(tid + i * 256) * 4, sa + (size_t)(tid + i * 256) * 4);
#pragma unroll
        for (int i = 0; i < 4; i++)
            cp16(d + 4096 + (size_t)(tid + i * 256) * 4, sb0 + (size_t)(tid + i * 256) * 4);
#pragma unroll
        for (int i = 0; i < 4; i++)
            cp16(d + 8192 + (size_t)(tid + i * 256) * 4, sb1 + (size_t)(tid + i * 256) * 4);
        asm volatile("cp.async.commit_group;");
    };

    stage_copy(0, 0);
    if (KT > 1) stage_copy(1, 1);

    const int ngb = (wn & 1) * 8;   // n8-group base within the 128-col B tile

    for (int kt = 0; kt < KT; kt++) {
        if (kt + 1 < KT) asm volatile("cp.async.wait_group 1;");
        else             asm volatile("cp.async.wait_group 0;");
        __syncthreads();
        if (kt + 2 < KT) stage_copy(kt + 2, (kt + 2) % STAGES);

        const float* As = sm + (kt % STAGES) * TILE_F;
        const float* Bsub = As + ((wn & 2) ? 8192 : 4096);
        const uint4* Au = (const uint4*)As;
        const uint4* Bu = (const uint4*)Bsub;

#pragma unroll
        for (int kp = 0; kp < 2; kp++) {
            uint4 bf[8];
#pragma unroll
            for (int nt = 0; nt < 8; nt++)
                bf[nt] = Bu[((kp * 16 + ngb + nt) * 8 + g) * 4 + tg];
#pragma unroll
            for (int s = 0; s < 2; s++) {
                const int ks = kp * 2 + s;
                uint4 a[4];
#pragma unroll
                for (int mt = 0; mt < 4; mt++)
                    a[mt] = Au[((ks * 8 + wm * 4 + mt) * 8 + g) * 4 + tg];
#pragma unroll
                for (int nt = 0; nt < 8; nt++) {
                    uint32_t b0 = s ? bf[nt].z : bf[nt].x;
                    uint32_t b1 = s ? bf[nt].w : bf[nt].y;
#pragma unroll
                    for (int mt = 0; mt < 4; mt++)
                        mma4(acc[mt][nt], a[mt], b0, b1);
                }
            }
        }
    }

    // epilogue: C normal row-major
    const int m0 = blockIdx.y * 128, n0 = blockIdx.x * 256;
#pragma unroll
    for (int mt = 0; mt < 4; mt++) {
#pragma unroll
        for (int half = 0; half < 2; half++) {
            int row = m0 + (wm * 4 + mt) * 16 + half * 8 + g;
#pragma unroll
            for (int nt = 0; nt < 8; nt++) {
                int col = n0 + wn * 64 + nt * 8 + tg * 2;
                float2 o;
                o.x = acc[mt][nt][half * 2 + 0];
                o.y = acc[mt][nt][half * 2 + 1];
                if (BIAS) { o.x += bias[col]; o.y += bias[col + 1]; }
                *(float2*)&C[(size_t)row * N + col] = o;
            }
        }
    }
}

// ------------------ norms ------------------
__global__ void zero_nsum() {
    int i = blockIdx.x * 256 + threadIdx.x;
    if (i < Bb * QKVC) g_nsum[i] = 0.f;
}

__global__ __launch_bounds__(256)
void partial_norm()
{
    int col = blockIdx.x * 256 + threadIdx.x;
    int ch = blockIdx.y, b = blockIdx.z;
    const float* p = g_qkv + ((size_t)b * Nn + (size_t)ch * CHUNK) * QKVC + col;
    float s = 0.f;
    for (int n = 0; n < CHUNK; n++) {
        float v = p[(size_t)n * QKVC];
        s += v * v;
    }
    atomicAdd(&g_nsum[b * QKVC + col], s);
}

__global__ void inv_norm() {
    int i = blockIdx.x * 256 + threadIdx.x;
    if (i < Bb * QKVC) {
        float nr = sqrtf(g_nsum[i]);
        g_inv[i] = 1.f / fmaxf(nr, EPS);
    }
}

// ------------------ attn partials via tf32 mma: per (h,b,chunk) ------------------
__global__ __launch_bounds__(256)
void attn_mma()
{
    int h = blockIdx.x, b = blockIdx.y, ch = blockIdx.z;
    __shared__ uint32_t Qs[32][136];
    __shared__ uint32_t Ks[32][136];

    const int tid  = threadIdx.x;
    const int warp = tid >> 5, lane = tid & 31;
    const int wm   = warp >> 1, wn = warp & 1;
    const int g    = lane >> 2, tg = lane & 3;

    float acc[2][8][4];
#pragma unroll
    for (int mt = 0; mt < 2; mt++)
#pragma unroll
        for (int nt = 0; nt < 8; nt++)
#pragma unroll
            for (int i = 0; i < 4; i++) acc[mt][nt][i] = 0.f;

    const float* qbase = g_qkv + ((size_t)b * Nn + (size_t)ch * CHUNK) * QKVC + h * HD;
    const float* kbase = qbase + DIM;

    const int lrow = tid >> 3;
    const int lcb  = (tid & 7) * 16;

    for (int n0 = 0; n0 < CHUNK; n0 += 32) {
        const float* qp = qbase + (size_t)(n0 + lrow) * QKVC + lcb;
        const float* kp = kbase + (size_t)(n0 + lrow) * QKVC + lcb;
#pragma unroll
        for (int i = 0; i < 4; i++) {
            float4 qv = *(const float4*)(qp + i * 4);
            Qs[lrow][lcb + i * 4 + 0] = f2tf32(qv.x);
            Qs[lrow][lcb + i * 4 + 1] = f2tf32(qv.y);
            Qs[lrow][lcb + i * 4 + 2] = f2tf32(qv.z);
            Qs[lrow][lcb + i * 4 + 3] = f2tf32(qv.w);
            float4 kv = *(const float4*)(kp + i * 4);
            Ks[lrow][lcb + i * 4 + 0] = f2tf32(kv.x);
            Ks[lrow][lcb + i * 4 + 1] = f2tf32(kv.y);
            Ks[lrow][lcb + i * 4 + 2] = f2tf32(kv.z);
            Ks[lrow][lcb + i * 4 + 3] = f2tf32(kv.w);
        }
        __syncthreads();
#pragma unroll
        for (int ks = 0; ks < 4; ks++) {
            const int kb = ks * 8;
            uint32_t af[2][4];
#pragma unroll
            for (int mt = 0; mt < 2; mt++) {
                int cm = wm * 32 + mt * 16 + g;
                af[mt][0] = Qs[kb + tg][cm];
                af[mt][1] = Qs[kb + tg][cm + 8];
                af[mt][2] = Qs[kb + tg + 4][cm];
                af[mt][3] = Qs[kb + tg + 4][cm + 8];
            }
            uint32_t bf[8][2];
#pragma unroll
            for (int nt = 0; nt < 8; nt++) {
                int nc = wn * 64 + nt * 8 + g;
                bf[nt][0] = Ks[kb + tg][nc];
                bf[nt][1] = Ks[kb + tg + 4][nc];
            }
#pragma unroll
            for (int mt = 0; mt < 2; mt++)
#pragma unroll
                for (int nt = 0; nt < 8; nt++) {
                    uint4 a = make_uint4(af[mt][0], af[mt][1], af[mt][2], af[mt][3]);
                    mma4(acc[mt][nt], a, bf[nt][0], bf[nt][1]);
                }
        }
        __syncthreads();
    }

    float* Pp = &g_P[ch][(size_t)(b * HEADS + h) * HD * HD];
#pragma unroll
    for (int mt = 0; mt < 2; mt++) {
#pragma unroll
        for (int half = 0; half < 2; half++) {
            int row = wm * 32 + mt * 16 + g + half * 8;
#pragma unroll
            for (int nt = 0; nt < 8; nt++) {
                int col = wn * 64 + nt * 8 + tg * 2;
                float2 o;
                o.x = acc[mt][nt][half * 2 + 0];
                o.y = acc[mt][nt][half * 2 + 1];
                *(float2*)&Pp[(size_t)row * HD + col] = o;
            }
        }
    }
}

// ------------------ sum partials + scale + softmax (writes tf32-rounded) ------------------
__global__ __launch_bounds__(128)
void softmax_rows(const float* __restrict__ temperature)
{
    int c = blockIdx.x, h = blockIdx.y, b = blockIdx.z;
    int d = threadIdx.x;
    size_t off = ((size_t)(b * HEADS + h) * HD + c) * HD + d;

    float s = 0.f;
#pragma unroll
    for (int ch = 0; ch < NCHUNK; ch++) s += g_P[ch][off];

    float scale = g_inv[b * QKVC + h * HD + c] *
                  g_inv[b * QKVC + DIM + h * HD + d] *
                  temperature[h];
    float val = s * scale;

    __shared__ float red[128];
    red[d] = val;
    __syncthreads();
    for (int o = 64; o >= 1; o >>= 1) {
        if (d < o) red[d] = fmaxf(red[d], red[d + o]);
        __syncthreads();
    }
    float mx = red[0];
    __syncthreads();
    float e = expf(val - mx);
    red[d] = e;
    __syncthreads();
    for (int o = 64; o >= 1; o >>= 1) {
        if (d < o) red[d] += red[d + o];
        __syncthreads();
    }
    float inv = 1.f / red[0];
    g_attn[off] = roundtf(e * inv);
}

// ------------------ out_tmp = attn @ v via tf32 mma; epilogue writes packed-A ------------------
__global__ __launch_bounds__(256)
void av_mma(const float* __restrict__ y)
{
    int mblk = blockIdx.x, h = blockIdx.y, b = blockIdx.z;
    __shared__ uint32_t Ys[128][36];
    __shared__ uint32_t At[128][36];

    const int tid  = threadIdx.x;
    const int warp = tid >> 5, lane = tid & 31;
    const int wm   = warp >> 1, wn = warp & 1;
    const int g    = lane >> 2, tg = lane & 3;

    float acc[2][8][4];
#pragma unroll
    for (int mt = 0; mt < 2; mt++)
#pragma unroll
        for (int nt = 0; nt < 8; nt++)
#pragma unroll
            for (int i = 0; i < 4; i++) acc[mt][nt][i] = 0.f;

    const int m0 = mblk * 128;
    const float* ybase = y + ((size_t)b * Nn + m0) * DIM + h * HD;
    const float* attnp = g_attn + (size_t)(b * HEADS + h) * HD * HD;

    const int lrow = tid >> 1;
    const int lcb  = (tid & 1) * 16;

    for (int d0 = 0; d0 < HD; d0 += 32) {
        const float* yp = ybase + (size_t)lrow * DIM + d0 + lcb;
        const float* ap = attnp + (size_t)lrow * HD + d0 + lcb;
#pragma unroll
        for (int i = 0; i < 4; i++) {
            float4 yv = *(const float4*)(yp + i * 4);
            Ys[lrow][lcb + i * 4 + 0] = f2tf32(yv.x);
            Ys[lrow][lcb + i * 4 + 1] = f2tf32(yv.y);
            Ys[lrow][lcb + i * 4 + 2] = f2tf32(yv.z);
            Ys[lrow][lcb + i * 4 + 3] = f2tf32(yv.w);
            *(uint4*)&At[lrow][lcb + i * 4] = *(const uint4*)(ap + i * 4);
        }
        __syncthreads();
#pragma unroll
        for (int ks = 0; ks < 4; ks++) {
            const int kb = ks * 8;
            uint32_t af[2][4];
#pragma unroll
            for (int mt = 0; mt < 2; mt++) {
                int mr = wm * 32 + mt * 16 + g;
                af[mt][0] = Ys[mr][kb + tg];
                af[mt][1] = Ys[mr + 8][kb + tg];
                af[mt][2] = Ys[mr][kb + tg + 4];
                af[mt][3] = Ys[mr + 8][kb + tg + 4];
            }
            uint32_t bf[8][2];
#pragma unroll
            for (int nt = 0; nt < 8; nt++) {
                int nc = wn * 64 + nt * 8 + g;
                bf[nt][0] = At[nc][kb + tg];
                bf[nt][1] = At[nc][kb + tg + 4];
            }
#pragma unroll
            for (int mt = 0; mt < 2; mt++)
#pragma unroll
                for (int nt = 0; nt < 8; nt++) {
                    uint4 a = make_uint4(af[mt][0], af[mt][1], af[mt][2], af[mt][3]);
                    mma4(acc[mt][nt], a, bf[nt][0], bf[nt][1]);
                }
        }
        __syncthreads();
    }

    // epilogue: write tf32-rounded into packed-A layout of g_tmp (feeds proj GEMM)
#pragma unroll
    for (int mt = 0; mt < 2; mt++) {
#pragma unroll
        for (int half = 0; half < 2; half++) {
            int row = m0 + wm * 32 + mt * 16 + g + half * 8;
            size_t gm = (size_t)b * Nn + row;
#pragma unroll
            for (int nt = 0; nt < 8; nt++) {
                int col = h * HD + wn * 64 + nt * 8 + tg * 2;
                g_tmp[aidx(gm, col,     DIM / 32)] = roundtf(acc[mt][nt][half * 2 + 0]);
                g_tmp[aidx(gm, col + 1, DIM / 32)] = roundtf(acc[mt][nt][half * 2 + 1]);
            }
        }
    }
}

// ------------------ launch ------------------
extern "C" void kernel_launch(void* const* d_in, const int* in_sizes, int n_in,
                              void* d_out, int out_size)
{
    const float* x     = (const float*)d_in[0];
    const float* y     = (const float*)d_in[1];
    const float* W_qkv = (const float*)d_in[2];
    const float* temp  = (const float*)d_in[3];
    const float* W_prj = (const float*)d_in[4];
    const float* b_prj = (const float*)d_in[5];
    float* out = (float*)d_out;

    float *qkv_p, *tmp_p, *xr_p, *wqkv_p, *wproj_p;
    cudaGetSymbolAddress((void**)&qkv_p, g_qkv);
    cudaGetSymbolAddress((void**)&tmp_p, g_tmp);
    cudaGetSymbolAddress((void**)&xr_p, g_xr);
    cudaGetSymbolAddress((void**)&wqkv_p, g_wqkv);
    cudaGetSymbolAddress((void**)&wproj_p, g_wproj);

    static bool attr_done = false;
    if (!attr_done) {
        cudaFuncSetAttribute(tf32gemm_pk<0>, cudaFuncAttributeMaxDynamicSharedMemorySize, GEMM_SMEM);
        cudaFuncSetAttribute(tf32gemm_pk<1>, cudaFuncAttributeMaxDynamicSharedMemorySize, GEMM_SMEM);
        attr_done = true;
    }

    // 0. pack operands (round to tf32 + fragment order)
    {
        size_t n4x = ((size_t)Bb * Nn * DIM) >> 2;
        pack_a<<<(unsigned)((n4x + 255) / 256), 256>>>(x, xr_p, Bb * Nn, DIM);
        size_t n4q = ((size_t)DIM * QKVC) >> 2;
        pack_b<<<(unsigned)((n4q + 255) / 256), 256>>>(W_qkv, wqkv_p, DIM, QKVC);
        size_t n4p = ((size_t)DIM * DIM) >> 2;
        pack_b<<<(unsigned)((n4p + 255) / 256), 256>>>(W_prj, wproj_p, DIM, DIM);
    }

    // 1. qkv = x @ W_qkv  (packed tf32 tensor cores, 128x256 blocks)
    tf32gemm_pk<0><<<dim3(QKVC / 256, (Bb * Nn) / 128), 256, GEMM_SMEM>>>(
        xr_p, wqkv_p, nullptr, qkv_p, Bb * Nn, QKVC, DIM);

    // 2. column norms of q,k over token dim
    zero_nsum<<<(Bb * QKVC + 255) / 256, 256>>>();
    partial_norm<<<dim3(QKVC / 256, NCHUNK, Bb), 256>>>();
    inv_norm<<<(Bb * QKVC + 255) / 256, 256>>>();

    // 3. attn partials (tf32 mma)
    attn_mma<<<dim3(HEADS, Bb, NCHUNK), 256>>>();

    // 4. sum + scale + softmax
    softmax_rows<<<dim3(HD, HEADS, Bb), 128>>>(temp);

    // 5. out_tmp = attn @ v (tf32 mma, writes packed-A)
    av_mma<<<dim3(Nn / 128, HEADS, Bb), 256>>>(y);

    // 6. out = out_tmp @ W_proj + b (packed tf32 tensor cores, 128x256 blocks)
    tf32gemm_pk<1><<<dim3(DIM / 256, (Bb * Nn) / 128), 256, GEMM_SMEM>>>(
        tmp_p, wproj_p, b_prj, out, Bb * Nn, DIM, DIM);
}

// round 15
// speedup vs baseline: 1.0011x; 1.0011x over previous
#include <cuda_runtime.h>
#include <math.h>
#include <stdint.h>

#define Bb 8
#define Nn 4096
#define DIM 768
#define HEADS 6
#define HD 128
#define QKVC 1536
#define NCHUNK 8
#define CHUNK (Nn/NCHUNK)   // 512
#define EPS 1e-12f

// ------------------ scratch (device globals: no allocs allowed) ------------------
__device__ float g_qkv[(size_t)Bb*Nn*QKVC];          // 201 MB (normal row-major)
__device__ float g_xr[(size_t)Bb*Nn*DIM];            // packed-A x (tf32), 100 MB
__device__ float g_wqkv[DIM*QKVC];                   // packed-B W_qkv (tf32)
__device__ float g_wproj[DIM*DIM];                   // packed-B W_proj (tf32)
__device__ float g_nsum[Bb*QKVC];
__device__ float g_inv[Bb*QKVC];
__device__ float g_P[NCHUNK][Bb*HEADS*HD*HD];        // attn partials, 25 MB
__device__ float g_attn[(size_t)Bb*HEADS*HD*HD];     // softmaxed attn (tf32-rounded)
__device__ float g_tmp[(size_t)Bb*Nn*DIM];           // packed-A pre-projection output

// ------------------ helpers ------------------
__device__ __forceinline__ uint32_t f2tf32(float x) {
    uint32_t r;
    asm("cvt.rna.tf32.f32 %0, %1;" : "=r"(r) : "f"(x));
    return r;
}
__device__ __forceinline__ float roundtf(float x) {
    return __uint_as_float(f2tf32(x));
}
__device__ __forceinline__ void cp16(void* dst, const void* src) {
    uint32_t d = (uint32_t)__cvta_generic_to_shared(dst);
    asm volatile("cp.async.cg.shared.global [%0], [%1], 16;" :: "r"(d), "l"(src));
}
__device__ __forceinline__ void mma4(float* c, const uint4& a, uint32_t b0, uint32_t b1) {
    asm volatile(
        "mma.sync.aligned.m16n8k8.row.col.f32.tf32.tf32.f32 "
        "{%0,%1,%2,%3},{%4,%5,%6,%7},{%8,%9},{%0,%1,%2,%3};"
        : "+f"(c[0]), "+f"(c[1]), "+f"(c[2]), "+f"(c[3])
        : "r"(a.x), "r"(a.y), "r"(a.z), "r"(a.w), "r"(b0), "r"(b1));
}

// packed-A element index: A[M][K] -> tiles [M/128][K/32][4096 floats]
// within tile: idx = (((ks*8+mg)*8+g)*4+tg)*4 + j,  j = khalf*2 + rowhalf
__device__ __forceinline__ size_t aidx(size_t m, int k, int KT) {
    size_t mt = m >> 7; int ml = (int)(m & 127);
    int kt = k >> 5, kl = k & 31;
    int ks = kl >> 3, kk = kl & 7, tg = kk & 3, kh = kk >> 2;
    int mg = ml >> 4, rh = (ml >> 3) & 1, gg = ml & 7;
    return ((mt * KT + kt) << 12) + (((((ks << 3) + mg) << 3) + gg) << 4) + (tg << 2) + (kh * 2 + rh);
}

// ------------------ pack kernels (round to tf32 + fragment order) ------------------
__global__ void pack_a(const float* __restrict__ src, float* __restrict__ dst,
                       int M, int K)
{
    int KT = K >> 5;
    size_t q = (size_t)blockIdx.x * 256 + threadIdx.x;
    size_t total = ((size_t)M * K) >> 2;
    if (q >= total) return;
    size_t tile = q >> 10;
    int qi = (int)(q & 1023);
    size_t mt = tile / KT; int kt = (int)(tile % KT);
    int tg = qi & 3, gg = (qi >> 2) & 7, mg = (qi >> 5) & 7, ks = qi >> 8;
    float4 o; float* po = (float*)&o;
#pragma unroll
    for (int j = 0; j < 4; j++) {
        int kh = j >> 1, rh = j & 1;
        size_t m = mt * 128 + mg * 16 + rh * 8 + gg;
        int k = kt * 32 + ks * 8 + kh * 4 + tg;
        po[j] = roundtf(src[m * K + k]);
    }
    ((float4*)dst)[q] = o;
}

// B pack: src [K,N] row-major -> packed tiles [N/128][K/32][4096]
// within tile: idx = (((kp*16+ng)*8+g)*4+tg)*4 + j,  j = (ks%2)*2 + khalf
__global__ void pack_b(const float* __restrict__ src, float* __restrict__ dst,
                       int K, int N)
{
    int KT = K >> 5;
    size_t q = (size_t)blockIdx.x * 256 + threadIdx.x;
    size_t total = ((size_t)K * N) >> 2;
    if (q >= total) return;
    size_t tile = q >> 10;
    int qi = (int)(q & 1023);
    size_t nt0 = tile / KT; int kt = (int)(tile % KT);
    int tg = qi & 3, gg = (qi >> 2) & 7, ng = (qi >> 5) & 15, kp = qi >> 9;
    float4 o; float* po = (float*)&o;
#pragma unroll
    for (int j = 0; j < 4; j++) {
        int s = j >> 1, kh = j & 1;
        int k = kt * 32 + (kp * 2 + s) * 8 + kh * 4 + tg;
        size_t n = nt0 * 128 + ng * 8 + gg;
        po[j] = roundtf(src[(size_t)k * N + n]);
    }
    ((float4*)dst)[q] = o;
}

// ------------------ packed tf32 GEMM: 128x256 block tile, 8 warps of 64x64 ------------------
#define STAGES 3
#define TILE_F 12288   // floats per stage: A 4096 + B0 4096 + B1 4096
#define GEMM_SMEM (STAGES * TILE_F * 4)

template<int BIAS>
__global__ __launch_bounds__(256, 1)
void tf32gemm_pk(const float* __restrict__ A, const float* __restrict__ B,
                 const float* __restrict__ bias, float* __restrict__ C,
                 int M, int N, int K)
{
    extern __shared__ float sm[];
    const int KT = K >> 5;
    const int tid  = threadIdx.x;
    const int warp = tid >> 5, lane = tid & 31;
    const int wm   = warp >> 2, wn = warp & 3;      // warp grid 2(m) x 4(n), tile 64x64
    const int g    = lane >> 2, tg = lane & 3;

    const float* Atile  = A + (size_t)blockIdx.y * KT * 4096;
    const float* Btile0 = B + (size_t)(blockIdx.x * 2 + 0) * KT * 4096;
    const float* Btile1 = B + (size_t)(blockIdx.x * 2 + 1) * KT * 4096;

    float acc[4][8][4];
#pragma unroll
    for (int mt = 0; mt < 4; mt++)
#pragma unroll
        for (int nt = 0; nt < 8; nt++)
#pragma unroll
            for (int i = 0; i < 4; i++) acc[mt][nt][i] = 0.f;

    // stage copy: 12288 floats = 3072 float4, 256 threads -> 12 cp16 each
    auto stage_copy = [&](int kt, int buf) {
        float* d = sm + buf * TILE_F;
        const float* sa  = Atile  + (size_t)kt * 4096;
        const float* sb0 = Btile0 + (size_t)kt * 4096;
        const float* sb1 = Btile1 + (size_t)kt * 4096;
#pragma unroll
        for (int i = 0; i < 4; i++)
            cp16(d + (size_t)(tid + i * 256) * 4, sa + (size_t)(tid + i * 256) * 4);
#pragma unroll
        for (int i = 0; i < 4; i++)
            cp16(d + 4096 + (size_t)(tid + i * 256) * 4, sb0 + (size_t)(tid + i * 256) * 4);
#pragma unroll
        for (int i = 0; i < 4; i++)
            cp16(d + 8192 + (size_t)(tid + i * 256) * 4, sb1 + (size_t)(tid + i * 256) * 4);
        asm volatile("cp.async.commit_group;");
    };

    stage_copy(0, 0);
    if (KT > 1) stage_copy(1, 1);

    const int ngb = (wn & 1) * 8;   // n8-group base within the 128-col B tile

    for (int kt = 0; kt < KT; kt++) {
        if (kt + 1 < KT) asm volatile("cp.async.wait_group 1;");
        else             asm volatile("cp.async.wait_group 0;");
        __syncthreads();
        if (kt + 2 < KT) stage_copy(kt + 2, (kt + 2) % STAGES);

        const float* As = sm + (kt % STAGES) * TILE_F;
        const float* Bsub = As + ((wn & 2) ? 8192 : 4096);
        const uint4* Au = (const uint4*)As;
        const uint4* Bu = (const uint4*)Bsub;

#pragma unroll
        for (int kp = 0; kp < 2; kp++) {
            uint4 bf[8];
#pragma unroll
            for (int nt = 0; nt < 8; nt++)
                bf[nt] = Bu[((kp * 16 + ngb + nt) * 8 + g) * 4 + tg];
#pragma unroll
            for (int s = 0; s < 2; s++) {
                const int ks = kp * 2 + s;
                uint4 a[4];
#pragma unroll
                for (int mt = 0; mt < 4; mt++)
                    a[mt] = Au[((ks * 8 + wm * 4 + mt) * 8 + g) * 4 + tg];
#pragma unroll
                for (int nt = 0; nt < 8; nt++) {
                    uint32_t b0 = s ? bf[nt].z : bf[nt].x;
                    uint32_t b1 = s ? bf[nt].w : bf[nt].y;
#pragma unroll
                    for (int mt = 0; mt < 4; mt++)
                        mma4(acc[mt][nt], a[mt], b0, b1);
                }
            }
        }
    }

    // epilogue: C normal row-major
    const int m0 = blockIdx.y * 128, n0 = blockIdx.x * 256;
#pragma unroll
    for (int mt = 0; mt < 4; mt++) {
#pragma unroll
        for (int half = 0; half < 2; half++) {
            int row = m0 + (wm * 4 + mt) * 16 + half * 8 + g;
#pragma unroll
            for (int nt = 0; nt < 8; nt++) {
                int col = n0 + wn * 64 + nt * 8 + tg * 2;
                float2 o;
                o.x = acc[mt][nt][half * 2 + 0];
                o.y = acc[mt][nt][half * 2 + 1];
                if (BIAS) { o.x += bias[col]; o.y += bias[col + 1]; }
                *(float2*)&C[(size_t)row * N + col] = o;
            }
        }
    }
}

// ------------------ norms ------------------
__global__ void zero_nsum() {
    int i = blockIdx.x * 256 + threadIdx.x;
    if (i < Bb * QKVC) g_nsum[i] = 0.f;
}

__global__ __launch_bounds__(256)
void partial_norm()
{
    int col = blockIdx.x * 256 + threadIdx.x;
    int ch = blockIdx.y, b = blockIdx.z;
    const float* p = g_qkv + ((size_t)b * Nn + (size_t)ch * CHUNK) * QKVC + col;
    float s = 0.f;
    for (int n = 0; n < CHUNK; n++) {
        float v = p[(size_t)n * QKVC];
        s += v * v;
    }
    atomicAdd(&g_nsum[b * QKVC + col], s);
}

__global__ void inv_norm() {
    int i = blockIdx.x * 256 + threadIdx.x;
    if (i < Bb * QKVC) {
        float nr = sqrtf(g_nsum[i]);
        g_inv[i] = 1.f / fmaxf(nr, EPS);
    }
}

// ------------------ attn partials via tf32 mma: per (h,b,chunk) ------------------
__global__ __launch_bounds__(256)
void attn_mma()
{
    int h = blockIdx.x, b = blockIdx.y, ch = blockIdx.z;
    __shared__ uint32_t Qs[32][136];
    __shared__ uint32_t Ks[32][136];

    const int tid  = threadIdx.x;
    const int warp = tid >> 5, lane = tid & 31;
    const int wm   = warp >> 1, wn = warp & 1;
    const int g    = lane >> 2, tg = lane & 3;

    float acc[2][8][4];
#pragma unroll
    for (int mt = 0; mt < 2; mt++)
#pragma unroll
        for (int nt = 0; nt < 8; nt++)
#pragma unroll
            for (int i = 0; i < 4; i++) acc[mt][nt][i] = 0.f;

    const float* qbase = g_qkv + ((size_t)b * Nn + (size_t)ch * CHUNK) * QKVC + h * HD;
    const float* kbase = qbase + DIM;

    const int lrow = tid >> 3;
    const int lcb  = (tid & 7) * 16;

    for (int n0 = 0; n0 < CHUNK; n0 += 32) {
        const float* qp = qbase + (size_t)(n0 + lrow) * QKVC + lcb;
        const float* kp = kbase + (size_t)(n0 + lrow) * QKVC + lcb;
#pragma unroll
        for (int i = 0; i < 4; i++) {
            float4 qv = *(const float4*)(qp + i * 4);
            Qs[lrow][lcb + i * 4 + 0] = f2tf32(qv.x);
            Qs[lrow][lcb + i * 4 + 1] = f2tf32(qv.y);
            Qs[lrow][lcb + i * 4 + 2] = f2tf32(qv.z);
            Qs[lrow][lcb + i * 4 + 3] = f2tf32(qv.w);
            float4 kv = *(const float4*)(kp + i * 4);
            Ks[lrow][lcb + i * 4 + 0] = f2tf32(kv.x);
            Ks[lrow][lcb + i * 4 + 1] = f2tf32(kv.y);
            Ks[lrow][lcb + i * 4 + 2] = f2tf32(kv.z);
            Ks[lrow][lcb + i * 4 + 3] = f2tf32(kv.w);
        }
        __syncthreads();
#pragma unroll
        for (int ks = 0; ks < 4; ks++) {
            const int kb = ks * 8;
            uint32_t af[2][4];
#pragma unroll
            for (int mt = 0; mt < 2; mt++) {
                int cm = wm * 32 + mt * 16 + g;
                af[mt][0] = Qs[kb + tg][cm];
                af[mt][1] = Qs[kb + tg][cm + 8];
                af[mt][2] = Qs[kb + tg + 4][cm];
                af[mt][3] = Qs[kb + tg + 4][cm + 8];
            }
            uint32_t bf[8][2];
#pragma unroll
            for (int nt = 0; nt < 8; nt++) {
                int nc = wn * 64 + nt * 8 + g;
                bf[nt][0] = Ks[kb + tg][nc];
                bf[nt][1] = Ks[kb + tg + 4][nc];
            }
#pragma unroll
            for (int mt = 0; mt < 2; mt++)
#pragma unroll
                for (int nt = 0; nt < 8; nt++) {
                    uint4 a = make_uint4(af[mt][0], af[mt][1], af[mt][2], af[mt][3]);
                    mma4(acc[mt][nt], a, bf[nt][0], bf[nt][1]);
                }
        }
        __syncthreads();
    }

    float* Pp = &g_P[ch][(size_t)(b * HEADS + h) * HD * HD];
#pragma unroll
    for (int mt = 0; mt < 2; mt++) {
#pragma unroll
        for (int half = 0; half < 2; half++) {
            int row = wm * 32 + mt * 16 + g + half * 8;
#pragma unroll
            for (int nt = 0; nt < 8; nt++) {
                int col = wn * 64 + nt * 8 + tg * 2;
                float2 o;
                o.x = acc[mt][nt][half * 2 + 0];
                o.y = acc[mt][nt][half * 2 + 1];
                *(float2*)&Pp[(size_t)row * HD + col] = o;
            }
        }
    }
}

// ------------------ sum partials + scale + softmax (writes tf32-rounded) ------------------
__global__ __launch_bounds__(128)
void softmax_rows(const float* __restrict__ temperature)
{
    int c = blockIdx.x, h = blockIdx.y, b = blockIdx.z;
    int d = threadIdx.x;
    size_t off = ((size_t)(b * HEADS + h) * HD + c) * HD + d;

    float s = 0.f;
#pragma unroll
    for (int ch = 0; ch < NCHUNK; ch++) s += g_P[ch][off];

    float scale = g_inv[b * QKVC + h * HD + c] *
                  g_inv[b * QKVC + DIM + h * HD + d] *
                  temperature[h];
    float val = s * scale;

    __shared__ float red[128];
    red[d] = val;
    __syncthreads();
    for (int o = 64; o >= 1; o >>= 1) {
        if (d < o) red[d] = fmaxf(red[d], red[d + o]);
        __syncthreads();
    }
    float mx = red[0];
    __syncthreads();
    float e = expf(val - mx);
    red[d] = e;
    __syncthreads();
    for (int o = 64; o >= 1; o >>= 1) {
        if (d < o) red[d] += red[d + o];
        __syncthreads();
    }
    float inv = 1.f / red[0];
    g_attn[off] = roundtf(e * inv);
}

// ------------------ out_tmp = attn @ v via tf32 mma; epilogue writes packed-A ------------------
__global__ __launch_bounds__(256)
void av_mma(const float* __restrict__ y)
{
    int mblk = blockIdx.x, h = blockIdx.y, b = blockIdx.z;
    __shared__ uint32_t Ys[128][36];
    __shared__ uint32_t At[128][36];

    const int tid  = threadIdx.x;
    const int warp = tid >> 5, lane = tid & 31;
    const int wm   = warp >> 1, wn = warp & 1;
    const int g    = lane >> 2, tg = lane & 3;

    float acc[2][8][4];
#pragma unroll
    for (int mt = 0; mt < 2; mt++)
#pragma unroll
        for (int nt = 0; nt < 8; nt++)
#pragma unroll
            for (int i = 0; i < 4; i++) acc[mt][nt][i] = 0.f;

    const int m0 = mblk * 128;
    const float* ybase = y + ((size_t)b * Nn + m0) * DIM + h * HD;
    const float* attnp = g_attn + (size_t)(b * HEADS + h) * HD * HD;

    const int lrow = tid >> 1;
    const int lcb  = (tid & 1) * 16;

    for (int d0 = 0; d0 < HD; d0 += 32) {
        const float* yp = ybase + (size_t)lrow * DIM + d0 + lcb;
        const float* ap = attnp + (size_t)lrow * HD + d0 + lcb;
#pragma unroll
        for (int i = 0; i < 4; i++) {
            float4 yv = *(const float4*)(yp + i * 4);
            Ys[lrow][lcb + i * 4 + 0] = f2tf32(yv.x);
            Ys[lrow][lcb + i * 4 + 1] = f2tf32(yv.y);
            Ys[lrow][lcb + i * 4 + 2] = f2tf32(yv.z);
            Ys[lrow][lcb + i * 4 + 3] = f2tf32(yv.w);
            *(uint4*)&At[lrow][lcb + i * 4] = *(const uint4*)(ap + i * 4);
        }
        __syncthreads();
#pragma unroll
        for (int ks = 0; ks < 4; ks++) {
            const int kb = ks * 8;
            uint32_t af[2][4];
#pragma unroll
            for (int mt = 0; mt < 2; mt++) {
                int mr = wm * 32 + mt * 16 + g;
                af[mt][0] = Ys[mr][kb + tg];
                af[mt][1] = Ys[mr + 8][kb + tg];
                af[mt][2] = Ys[mr][kb + tg + 4];
                af[mt][3] = Ys[mr + 8][kb + tg + 4];
            }
            uint32_t bf[8][2];
#pragma unroll
            for (int nt = 0; nt < 8; nt++) {
                int nc = wn * 64 + nt * 8 + g;
                bf[nt][0] = At[nc][kb + tg];
                bf[nt][1] = At[nc][kb + tg + 4];
            }
#pragma unroll
            for (int mt = 0; mt < 2; mt++)
#pragma unroll
                for (int nt = 0; nt < 8; nt++) {
                    uint4 a = make_uint4(af[mt][0], af[mt][1], af[mt][2], af[mt][3]);
                    mma4(acc[mt][nt], a, bf[nt][0], bf[nt][1]);
                }
        }
        __syncthreads();
    }

    // epilogue: write tf32-rounded into packed-A layout of g_tmp (feeds proj GEMM)
#pragma unroll
    for (int mt = 0; mt < 2; mt++) {
#pragma unroll
        for (int half = 0; half < 2; half++) {
            int row = m0 + wm * 32 + mt * 16 + g + half * 8;
            size_t gm = (size_t)b * Nn + row;
#pragma unroll
            for (int nt = 0; nt < 8; nt++) {
                int col = h * HD + wn * 64 + nt * 8 + tg * 2;
                g_tmp[aidx(gm, col,     DIM / 32)] = roundtf(acc[mt][nt][half * 2 + 0]);
                g_tmp[aidx(gm, col + 1, DIM / 32)] = roundtf(acc[mt][nt][half * 2 + 1]);
            }
        }
    }
}

// ------------------ launch ------------------
extern "C" void kernel_launch(void* const* d_in, const int* in_sizes, int n_in,
                              void* d_out, int out_size)
{
    const float* x     = (const float*)d_in[0];
    const float* y     = (const float*)d_in[1];
    const float* W_qkv = (const float*)d_in[2];
    const float* temp  = (const float*)d_in[3];
    const float* W_prj = (const float*)d_in[4];
    const float* b_prj = (const float*)d_in[5];
    float* out = (float*)d_out;

    float *qkv_p, *tmp_p, *xr_p, *wqkv_p, *wproj_p;
    cudaGetSymbolAddress((void**)&qkv_p, g_qkv);
    cudaGetSymbolAddress((void**)&tmp_p, g_tmp);
    cudaGetSymbolAddress((void**)&xr_p, g_xr);
    cudaGetSymbolAddress((void**)&wqkv_p, g_wqkv);
    cudaGetSymbolAddress((void**)&wproj_p, g_wproj);

    static bool attr_done = false;
    if (!attr_done) {
        cudaFuncSetAttribute(tf32gemm_pk<0>, cudaFuncAttributeMaxDynamicSharedMemorySize, GEMM_SMEM);
        cudaFuncSetAttribute(tf32gemm_pk<1>, cudaFuncAttributeMaxDynamicSharedMemorySize, GEMM_SMEM);
        attr_done = true;
    }

    // 0. pack operands (round to tf32 + fragment order)
    {
        size_t n4x = ((size_t)Bb * Nn * DIM) >> 2;
        pack_a<<<(unsigned)((n4x + 255) / 256), 256>>>(x, xr_p, Bb * Nn, DIM);
        size_t n4q = ((size_t)DIM * QKVC) >> 2;
        pack_b<<<(unsigned)((n4q + 255) / 256), 256>>>(W_qkv, wqkv_p, DIM, QKVC);
        size_t n4p = ((size_t)DIM * DIM) >> 2;
        pack_b<<<(unsigned)((n4p + 255) / 256), 256>>>(W_prj, wproj_p, DIM, DIM);
    }

    // 1. qkv = x @ W_qkv  (packed tf32 tensor cores, 128x256 blocks)
    tf32gemm_pk<0><<<dim3(QKVC / 256, (Bb * Nn) / 128), 256, GEMM_SMEM>>>(
        xr_p, wqkv_p, nullptr, qkv_p, Bb * Nn, QKVC, DIM);

    // 2. column norms of q,k over token dim
    zero_nsum<<<(Bb * QKVC + 255) / 256, 256>>>();
    partial_norm<<<dim3(QKVC / 256, NCHUNK, Bb), 256>>>();
    inv_norm<<<(Bb * QKVC + 255) / 256, 256>>>();

    // 3. attn partials (tf32 mma)
    attn_mma<<<dim3(HEADS, Bb, NCHUNK), 256>>>();

    // 4. sum + scale + softmax
    softmax_rows<<<dim3(HD, HEADS, Bb), 128>>>(temp);

    // 5. out_tmp = attn @ v (tf32 mma, writes packed-A)
    av_mma<<<dim3(Nn / 128, HEADS, Bb), 256>>>(y);

    // 6. out = out_tmp @ W_proj + b (packed tf32 tensor cores, 128x256 blocks)
    tf32gemm_pk<1><<<dim3(DIM / 256, (Bb * Nn) / 128), 256, GEMM_SMEM>>>(
        tmp_p, wproj_p, b_prj, out, Bb * Nn, DIM, DIM);
}

// round 16
// speedup vs baseline: 1.0855x; 1.0843x over previous
#include <cuda_runtime.h>
#include <math.h>
#include <stdint.h>

#define Bb 8
#define Nn 4096
#define DIM 768
#define HEADS 6
#define HD 128
#define QKVC 1536
#define NCHUNK 8
#define CHUNK (Nn/NCHUNK)   // 512
#define EPS 1e-12f

// ------------------ scratch (device globals: no allocs allowed) ------------------
__device__ float g_qkv[(size_t)Bb*Nn*QKVC];          // 201 MB (normal row-major)
__device__ float g_xr[(size_t)Bb*Nn*DIM];            // packed-A x (tf32), 100 MB
__device__ float g_wqkv[DIM*QKVC];                   // packed-B W_qkv (tf32)
__device__ float g_wproj[DIM*DIM];                   // packed-B W_proj (tf32)
__device__ float g_nsum[Bb*QKVC];
__device__ float g_inv[Bb*QKVC];
__device__ float g_P[NCHUNK][Bb*HEADS*HD*HD];        // attn partials, 25 MB
__device__ float g_attn[(size_t)Bb*HEADS*HD*HD];     // softmaxed attn (tf32-rounded)
__device__ float g_tmp[(size_t)Bb*Nn*DIM];           // packed-A pre-projection output

// ------------------ helpers ------------------
__device__ __forceinline__ uint32_t f2tf32(float x) {
    uint32_t r;
    asm("cvt.rna.tf32.f32 %0, %1;" : "=r"(r) : "f"(x));
    return r;
}
__device__ __forceinline__ float roundtf(float x) {
    return __uint_as_float(f2tf32(x));
}
__device__ __forceinline__ void cp16(void* dst, const void* src) {
    uint32_t d = (uint32_t)__cvta_generic_to_shared(dst);
    asm volatile("cp.async.cg.shared.global [%0], [%1], 16;" :: "r"(d), "l"(src));
}
__device__ __forceinline__ void mma4(float* c, const uint4& a, uint32_t b0, uint32_t b1) {
    asm volatile(
        "mma.sync.aligned.m16n8k8.row.col.f32.tf32.tf32.f32 "
        "{%0,%1,%2,%3},{%4,%5,%6,%7},{%8,%9},{%0,%1,%2,%3};"
        : "+f"(c[0]), "+f"(c[1]), "+f"(c[2]), "+f"(c[3])
        : "r"(a.x), "r"(a.y), "r"(a.z), "r"(a.w), "r"(b0), "r"(b1));
}

// packed-A element index: A[M][K] -> tiles [M/128][K/32][4096 floats]
// within tile: idx = (((ks*8+mg)*8+g)*4+tg)*4 + j,  j = khalf*2 + rowhalf
__device__ __forceinline__ size_t aidx(size_t m, int k, int KT) {
    size_t mt = m >> 7; int ml = (int)(m & 127);
    int kt = k >> 5, kl = k & 31;
    int ks = kl >> 3, kk = kl & 7, tg = kk & 3, kh = kk >> 2;
    int mg = ml >> 4, rh = (ml >> 3) & 1, gg = ml & 7;
    return ((mt * KT + kt) << 12) + (((((ks << 3) + mg) << 3) + gg) << 4) + (tg << 2) + (kh * 2 + rh);
}

// ------------------ pack kernels (round to tf32 + fragment order) ------------------
__global__ void pack_a(const float* __restrict__ src, float* __restrict__ dst,
                       int M, int K)
{
    int KT = K >> 5;
    size_t q = (size_t)blockIdx.x * 256 + threadIdx.x;
    size_t total = ((size_t)M * K) >> 2;
    if (q >= total) return;
    size_t tile = q >> 10;
    int qi = (int)(q & 1023);
    size_t mt = tile / KT; int kt = (int)(tile % KT);
    int tg = qi & 3, gg = (qi >> 2) & 7, mg = (qi >> 5) & 7, ks = qi >> 8;
    float4 o; float* po = (float*)&o;
#pragma unroll
    for (int j = 0; j < 4; j++) {
        int kh = j >> 1, rh = j & 1;
        size_t m = mt * 128 + mg * 16 + rh * 8 + gg;
        int k = kt * 32 + ks * 8 + kh * 4 + tg;
        po[j] = roundtf(src[m * K + k]);
    }
    ((float4*)dst)[q] = o;
}

// B pack: src [K,N] row-major -> packed tiles [N/128][K/32][4096]
// within tile: idx = (((kp*16+ng)*8+g)*4+tg)*4 + j,  j = (ks%2)*2 + khalf
__global__ void pack_b(const float* __restrict__ src, float* __restrict__ dst,
                       int K, int N)
{
    int KT = K >> 5;
    size_t q = (size_t)blockIdx.x * 256 + threadIdx.x;
    size_t total = ((size_t)K * N) >> 2;
    if (q >= total) return;
    size_t tile = q >> 10;
    int qi = (int)(q & 1023);
    size_t nt0 = tile / KT; int kt = (int)(tile % KT);
    int tg = qi & 3, gg = (qi >> 2) & 7, ng = (qi >> 5) & 15, kp = qi >> 9;
    float4 o; float* po = (float*)&o;
#pragma unroll
    for (int j = 0; j < 4; j++) {
        int s = j >> 1, kh = j & 1;
        int k = kt * 32 + (kp * 2 + s) * 8 + kh * 4 + tg;
        size_t n = nt0 * 128 + ng * 8 + gg;
        po[j] = roundtf(src[(size_t)k * N + n]);
    }
    ((float4*)dst)[q] = o;
}

// ------------------ packed tf32 GEMM: 128x128 block, 4 warps of 64x64, 3-stage ------------------
#define STAGES 3
#define TILE_F 8192    // floats per stage: A 4096 + B 4096
#define GEMM_SMEM (STAGES * TILE_F * 4)

template<int BIAS>
__global__ __launch_bounds__(128, 2)
void tf32gemm_pk(const float* __restrict__ A, const float* __restrict__ B,
                 const float* __restrict__ bias, float* __restrict__ C,
                 int M, int N, int K)
{
    extern __shared__ float sm[];
    const int KT = K >> 5;
    const int tid  = threadIdx.x;
    const int warp = tid >> 5, lane = tid & 31;
    const int wm   = warp >> 1, wn = warp & 1;      // warp grid 2(m) x 2(n), tile 64x64
    const int g    = lane >> 2, tg = lane & 3;

    const float* Atile = A + (size_t)blockIdx.y * KT * 4096;
    const float* Btile = B + (size_t)blockIdx.x * KT * 4096;

    float acc[4][8][4];
#pragma unroll
    for (int mt = 0; mt < 4; mt++)
#pragma unroll
        for (int nt = 0; nt < 8; nt++)
#pragma unroll
            for (int i = 0; i < 4; i++) acc[mt][nt][i] = 0.f;

    // stage copy: 8192 floats = 2048 float4, 128 threads -> 16 cp16 each
    auto stage_copy = [&](int kt, int buf) {
        float* d = sm + buf * TILE_F;
        const float* sa = Atile + (size_t)kt * 4096;
        const float* sb = Btile + (size_t)kt * 4096;
#pragma unroll
        for (int i = 0; i < 8; i++)
            cp16(d + (size_t)(tid + i * 128) * 4, sa + (size_t)(tid + i * 128) * 4);
#pragma unroll
        for (int i = 0; i < 8; i++)
            cp16(d + 4096 + (size_t)(tid + i * 128) * 4, sb + (size_t)(tid + i * 128) * 4);
        asm volatile("cp.async.commit_group;");
    };

    stage_copy(0, 0);
    if (KT > 1) stage_copy(1, 1);

    for (int kt = 0; kt < KT; kt++) {
        if (kt + 1 < KT) asm volatile("cp.async.wait_group 1;");
        else             asm volatile("cp.async.wait_group 0;");
        __syncthreads();
        if (kt + 2 < KT) stage_copy(kt + 2, (kt + 2) % STAGES);

        const float* As = sm + (kt % STAGES) * TILE_F;
        const uint4* Au = (const uint4*)As;
        const uint4* Bu = (const uint4*)(As + 4096);

#pragma unroll
        for (int kp = 0; kp < 2; kp++) {
            uint4 bf[8];
#pragma unroll
            for (int nt = 0; nt < 8; nt++)
                bf[nt] = Bu[((kp * 16 + wn * 8 + nt) * 8 + g) * 4 + tg];
#pragma unroll
            for (int s = 0; s < 2; s++) {
                const int ks = kp * 2 + s;
                uint4 a[4];
#pragma unroll
                for (int mt = 0; mt < 4; mt++)
                    a[mt] = Au[((ks * 8 + wm * 4 + mt) * 8 + g) * 4 + tg];
#pragma unroll
                for (int nt = 0; nt < 8; nt++) {
                    uint32_t b0 = s ? bf[nt].z : bf[nt].x;
                    uint32_t b1 = s ? bf[nt].w : bf[nt].y;
#pragma unroll
                    for (int mt = 0; mt < 4; mt++)
                        mma4(acc[mt][nt], a[mt], b0, b1);
                }
            }
        }
    }

    // epilogue: C normal row-major
    const int m0 = blockIdx.y * 128, n0 = blockIdx.x * 128;
#pragma unroll
    for (int mt = 0; mt < 4; mt++) {
#pragma unroll
        for (int half = 0; half < 2; half++) {
            int row = m0 + (wm * 4 + mt) * 16 + half * 8 + g;
#pragma unroll
            for (int nt = 0; nt < 8; nt++) {
                int col = n0 + wn * 64 + nt * 8 + tg * 2;
                float2 o;
                o.x = acc[mt][nt][half * 2 + 0];
                o.y = acc[mt][nt][half * 2 + 1];
                if (BIAS) { o.x += bias[col]; o.y += bias[col + 1]; }
                *(float2*)&C[(size_t)row * N + col] = o;
            }
        }
    }
}

// ------------------ norms ------------------
__global__ void zero_nsum() {
    int i = blockIdx.x * 256 + threadIdx.x;
    if (i < Bb * QKVC) g_nsum[i] = 0.f;
}

__global__ __launch_bounds__(256)
void partial_norm()
{
    int col = blockIdx.x * 256 + threadIdx.x;
    int ch = blockIdx.y, b = blockIdx.z;
    const float* p = g_qkv + ((size_t)b * Nn + (size_t)ch * CHUNK) * QKVC + col;
    float s = 0.f;
    for (int n = 0; n < CHUNK; n++) {
        float v = p[(size_t)n * QKVC];
        s += v * v;
    }
    atomicAdd(&g_nsum[b * QKVC + col], s);
}

__global__ void inv_norm() {
    int i = blockIdx.x * 256 + threadIdx.x;
    if (i < Bb * QKVC) {
        float nr = sqrtf(g_nsum[i]);
        g_inv[i] = 1.f / fmaxf(nr, EPS);
    }
}

// ------------------ attn partials via tf32 mma: per (h,b,chunk) ------------------
__global__ __launch_bounds__(256)
void attn_mma()
{
    int h = blockIdx.x, b = blockIdx.y, ch = blockIdx.z;
    __shared__ uint32_t Qs[32][136];
    __shared__ uint32_t Ks[32][136];

    const int tid  = threadIdx.x;
    const int warp = tid >> 5, lane = tid & 31;
    const int wm   = warp >> 1, wn = warp & 1;
    const int g    = lane >> 2, tg = lane & 3;

    float acc[2][8][4];
#pragma unroll
    for (int mt = 0; mt < 2; mt++)
#pragma unroll
        for (int nt = 0; nt < 8; nt++)
#pragma unroll
            for (int i = 0; i < 4; i++) acc[mt][nt][i] = 0.f;

    const float* qbase = g_qkv + ((size_t)b * Nn + (size_t)ch * CHUNK) * QKVC + h * HD;
    const float* kbase = qbase + DIM;

    const int lrow = tid >> 3;
    const int lcb  = (tid & 7) * 16;

    for (int n0 = 0; n0 < CHUNK; n0 += 32) {
        const float* qp = qbase + (size_t)(n0 + lrow) * QKVC + lcb;
        const float* kp = kbase + (size_t)(n0 + lrow) * QKVC + lcb;
#pragma unroll
        for (int i = 0; i < 4; i++) {
            float4 qv = *(const float4*)(qp + i * 4);
            Qs[lrow][lcb + i * 4 + 0] = f2tf32(qv.x);
            Qs[lrow][lcb + i * 4 + 1] = f2tf32(qv.y);
            Qs[lrow][lcb + i * 4 + 2] = f2tf32(qv.z);
            Qs[lrow][lcb + i * 4 + 3] = f2tf32(qv.w);
            float4 kv = *(const float4*)(kp + i * 4);
            Ks[lrow][lcb + i * 4 + 0] = f2tf32(kv.x);
            Ks[lrow][lcb + i * 4 + 1] = f2tf32(kv.y);
            Ks[lrow][lcb + i * 4 + 2] = f2tf32(kv.z);
            Ks[lrow][lcb + i * 4 + 3] = f2tf32(kv.w);
        }
        __syncthreads();
#pragma unroll
        for (int ks = 0; ks < 4; ks++) {
            const int kb = ks * 8;
            uint32_t af[2][4];
#pragma unroll
            for (int mt = 0; mt < 2; mt++) {
                int cm = wm * 32 + mt * 16 + g;
                af[mt][0] = Qs[kb + tg][cm];
                af[mt][1] = Qs[kb + tg][cm + 8];
                af[mt][2] = Qs[kb + tg + 4][cm];
                af[mt][3] = Qs[kb + tg + 4][cm + 8];
            }
            uint32_t bf[8][2];
#pragma unroll
            for (int nt = 0; nt < 8; nt++) {
                int nc = wn * 64 + nt * 8 + g;
                bf[nt][0] = Ks[kb + tg][nc];
                bf[nt][1] = Ks[kb + tg + 4][nc];
            }
#pragma unroll
            for (int mt = 0; mt < 2; mt++)
#pragma unroll
                for (int nt = 0; nt < 8; nt++) {
                    uint4 a = make_uint4(af[mt][0], af[mt][1], af[mt][2], af[mt][3]);
                    mma4(acc[mt][nt], a, bf[nt][0], bf[nt][1]);
                }
        }
        __syncthreads();
    }

    float* Pp = &g_P[ch][(size_t)(b * HEADS + h) * HD * HD];
#pragma unroll
    for (int mt = 0; mt < 2; mt++) {
#pragma unroll
        for (int half = 0; half < 2; half++) {
            int row = wm * 32 + mt * 16 + g + half * 8;
#pragma unroll
            for (int nt = 0; nt < 8; nt++) {
                int col = wn * 64 + nt * 8 + tg * 2;
                float2 o;
                o.x = acc[mt][nt][half * 2 + 0];
                o.y = acc[mt][nt][half * 2 + 1];
                *(float2*)&Pp[(size_t)row * HD + col] = o;
            }
        }
    }
}

// ------------------ sum partials + scale + softmax (writes tf32-rounded) ------------------
__global__ __launch_bounds__(128)
void softmax_rows(const float* __restrict__ temperature)
{
    int c = blockIdx.x, h = blockIdx.y, b = blockIdx.z;
    int d = threadIdx.x;
    size_t off = ((size_t)(b * HEADS + h) * HD + c) * HD + d;

    float s = 0.f;
#pragma unroll
    for (int ch = 0; ch < NCHUNK; ch++) s += g_P[ch][off];

    float scale = g_inv[b * QKVC + h * HD + c] *
                  g_inv[b * QKVC + DIM + h * HD + d] *
                  temperature[h];
    float val = s * scale;

    __shared__ float red[128];
    red[d] = val;
    __syncthreads();
    for (int o = 64; o >= 1; o >>= 1) {
        if (d < o) red[d] = fmaxf(red[d], red[d + o]);
        __syncthreads();
    }
    float mx = red[0];
    __syncthreads();
    float e = expf(val - mx);
    red[d] = e;
    __syncthreads();
    for (int o = 64; o >= 1; o >>= 1) {
        if (d < o) red[d] += red[d + o];
        __syncthreads();
    }
    float inv = 1.f / red[0];
    g_attn[off] = roundtf(e * inv);
}

// ------------------ out_tmp = attn @ v via tf32 mma; epilogue writes packed-A ------------------
__global__ __launch_bounds__(256)
void av_mma(const float* __restrict__ y)
{
    int mblk = blockIdx.x, h = blockIdx.y, b = blockIdx.z;
    __shared__ uint32_t Ys[128][36];
    __shared__ uint32_t At[128][36];

    const int tid  = threadIdx.x;
    const int warp = tid >> 5, lane = tid & 31;
    const int wm   = warp >> 1, wn = warp & 1;
    const int g    = lane >> 2, tg = lane & 3;

    float acc[2][8][4];
#pragma unroll
    for (int mt = 0; mt < 2; mt++)
#pragma unroll
        for (int nt = 0; nt < 8; nt++)
#pragma unroll
            for (int i = 0; i < 4; i++) acc[mt][nt][i] = 0.f;

    const int m0 = mblk * 128;
    const float* ybase = y + ((size_t)b * Nn + m0) * DIM + h * HD;
    const float* attnp = g_attn + (size_t)(b * HEADS + h) * HD * HD;

    const int lrow = tid >> 1;
    const int lcb  = (tid & 1) * 16;

    for (int d0 = 0; d0 < HD; d0 += 32) {
        const float* yp = ybase + (size_t)lrow * DIM + d0 + lcb;
        const float* ap = attnp + (size_t)lrow * HD + d0 + lcb;
#pragma unroll
        for (int i = 0; i < 4; i++) {
            float4 yv = *(const float4*)(yp + i * 4);
            Ys[lrow][lcb + i * 4 + 0] = f2tf32(yv.x);
            Ys[lrow][lcb + i * 4 + 1] = f2tf32(yv.y);
            Ys[lrow][lcb + i * 4 + 2] = f2tf32(yv.z);
            Ys[lrow][lcb + i * 4 + 3] = f2tf32(yv.w);
            *(uint4*)&At[lrow][lcb + i * 4] = *(const uint4*)(ap + i * 4);
        }
        __syncthreads();
#pragma unroll
        for (int ks = 0; ks < 4; ks++) {
            const int kb = ks * 8;
            uint32_t af[2][4];
#pragma unroll
            for (int mt = 0; mt < 2; mt++) {
                int mr = wm * 32 + mt * 16 + g;
                af[mt][0] = Ys[mr][kb + tg];
                af[mt][1] = Ys[mr + 8][kb + tg];
                af[mt][2] = Ys[mr][kb + tg + 4];
                af[mt][3] = Ys[mr + 8][kb + tg + 4];
            }
            uint32_t bf[8][2];
#pragma unroll
            for (int nt = 0; nt < 8; nt++) {
                int nc = wn * 64 + nt * 8 + g;
                bf[nt][0] = At[nc][kb + tg];
                bf[nt][1] = At[nc][kb + tg + 4];
            }
#pragma unroll
            for (int mt = 0; mt < 2; mt++)
#pragma unroll
                for (int nt = 0; nt < 8; nt++) {
                    uint4 a = make_uint4(af[mt][0], af[mt][1], af[mt][2], af[mt][3]);
                    mma4(acc[mt][nt], a, bf[nt][0], bf[nt][1]);
                }
        }
        __syncthreads();
    }

    // epilogue: write tf32-rounded into packed-A layout of g_tmp (feeds proj GEMM)
#pragma unroll
    for (int mt = 0; mt < 2; mt++) {
#pragma unroll
        for (int half = 0; half < 2; half++) {
            int row = m0 + wm * 32 + mt * 16 + g + half * 8;
            size_t gm = (size_t)b * Nn + row;
#pragma unroll
            for (int nt = 0; nt < 8; nt++) {
                int col = h * HD + wn * 64 + nt * 8 + tg * 2;
                g_tmp[aidx(gm, col,     DIM / 32)] = roundtf(acc[mt][nt][half * 2 + 0]);
                g_tmp[aidx(gm, col + 1, DIM / 32)] = roundtf(acc[mt][nt][half * 2 + 1]);
            }
        }
    }
}

// ------------------ launch ------------------
extern "C" void kernel_launch(void* const* d_in, const int* in_sizes, int n_in,
                              void* d_out, int out_size)
{
    const float* x     = (const float*)d_in[0];
    const float* y     = (const float*)d_in[1];
    const float* W_qkv = (const float*)d_in[2];
    const float* temp  = (const float*)d_in[3];
    const float* W_prj = (const float*)d_in[4];
    const float* b_prj = (const float*)d_in[5];
    float* out = (float*)d_out;

    float *qkv_p, *tmp_p, *xr_p, *wqkv_p, *wproj_p;
    cudaGetSymbolAddress((void**)&qkv_p, g_qkv);
    cudaGetSymbolAddress((void**)&tmp_p, g_tmp);
    cudaGetSymbolAddress((void**)&xr_p, g_xr);
    cudaGetSymbolAddress((void**)&wqkv_p, g_wqkv);
    cudaGetSymbolAddress((void**)&wproj_p, g_wproj);

    static bool attr_done = false;
    if (!attr_done) {
        cudaFuncSetAttribute(tf32gemm_pk<0>, cudaFuncAttributeMaxDynamicSharedMemorySize, GEMM_SMEM);
        cudaFuncSetAttribute(tf32gemm_pk<1>, cudaFuncAttributeMaxDynamicSharedMemorySize, GEMM_SMEM);
        attr_done = true;
    }

    // 0. pack operands (round to tf32 + fragment order)
    {
        size_t n4x = ((size_t)Bb * Nn * DIM) >> 2;
        pack_a<<<(unsigned)((n4x + 255) / 256), 256>>>(x, xr_p, Bb * Nn, DIM);
        size_t n4q = ((size_t)DIM * QKVC) >> 2;
        pack_b<<<(unsigned)((n4q + 255) / 256), 256>>>(W_qkv, wqkv_p, DIM, QKVC);
        size_t n4p = ((size_t)DIM * DIM) >> 2;
        pack_b<<<(unsigned)((n4p + 255) / 256), 256>>>(W_prj, wproj_p, DIM, DIM);
    }

    // 1. qkv = x @ W_qkv  (packed tf32 tensor cores, 4-warp 128x128 blocks)
    tf32gemm_pk<0><<<dim3(QKVC / 128, (Bb * Nn) / 128), 128, GEMM_SMEM>>>(
        xr_p, wqkv_p, nullptr, qkv_p, Bb * Nn, QKVC, DIM);

    // 2. column norms of q,k over token dim
    zero_nsum<<<(Bb * QKVC + 255) / 256, 256>>>();
    partial_norm<<<dim3(QKVC / 256, NCHUNK, Bb), 256>>>();
    inv_norm<<<(Bb * QKVC + 255) / 256, 256>>>();

    // 3. attn partials (tf32 mma)
    attn_mma<<<dim3(HEADS, Bb, NCHUNK), 256>>>();

    // 4. sum + scale + softmax
    softmax_rows<<<dim3(HD, HEADS, Bb), 128>>>(temp);

    // 5. out_tmp = attn @ v (tf32 mma, writes packed-A)
    av_mma<<<dim3(Nn / 128, HEADS, Bb), 256>>>(y);

    // 6. out = out_tmp @ W_proj + b (packed tf32 tensor cores, 4-warp 128x128 blocks)
    tf32gemm_pk<1><<<dim3(DIM / 128, (Bb * Nn) / 128), 128, GEMM_SMEM>>>(
        tmp_p, wproj_p, b_prj, out, Bb * Nn, DIM, DIM);
}